// round 12
// baseline (speedup 1.0000x reference)
#include <cuda_runtime.h>
#include <cuda_bf16.h>
#include <stdint.h>

// Problem constants
#define N_TOK   2048
#define DIM     512
#define HOUT    512
#define NEXP    16

// GEMM tiling: CTA 64x32, 4 warps of 32x16
#define BM      64
#define BN      32
#define KC      32
#define NCHUNK  (DIM / KC)   // 16
#define NSTAGE  3            // A-tile cp.async stages
#define MAX_TILES 48         // 2048/64 + 16 worst case
#define PAD_TOK (MAX_TILES * BM)   // 3072

// smem layout (bf16 elems)
#define LDSA    40                          // KC+8 pad (conflict-free)
#define LDSB    40                          // BN+8 pad (80B rows: conflict-free)
#define A_ST_E  (2 * BM * LDSA)             // hi+lo per A stage = 5120
#define A_LO_E  (BM * LDSA)                 // 2560
#define B0_E    (NSTAGE * A_ST_E)           // 15360
#define B_BUF_E (2 * KC * LDSB)             // hi+lo per B buf = 2560
#define B_LO_E  (KC * LDSB)                 // 1280
#define SMEM_BYTES ((B0_E + 2 * B_BUF_E) * 2)   // 40960

// X split scratch (W converted on the fly)
#define XELEMS (N_TOK * DIM)
__device__ uint4 g_Xhi4[XELEMS / 8];
__device__ uint4 g_Xlo4[XELEMS / 8];

__device__ int g_order[PAD_TOK];
__device__ int g_tile_expert[MAX_TILES];

// ---------------------------------------------------------------------------
// PTX helpers (sm_80-era only; tcgen05 is gated off by the sm_103 ptxas target)
// ---------------------------------------------------------------------------
__device__ __forceinline__ uint32_t smem_u32(const void* p) {
    uint32_t a;
    asm("{ .reg .u64 t; cvta.to.shared.u64 t, %1; cvt.u32.u64 %0, t; }"
        : "=r"(a) : "l"(p));
    return a;
}
__device__ __forceinline__ void ldsm_x4(uint32_t* r, uint32_t addr) {
    asm volatile("ldmatrix.sync.aligned.m8n8.x4.shared.b16 {%0,%1,%2,%3}, [%4];"
                 : "=r"(r[0]), "=r"(r[1]), "=r"(r[2]), "=r"(r[3]) : "r"(addr));
}
__device__ __forceinline__ void ldsm_x4_t(uint32_t* r, uint32_t addr) {
    asm volatile("ldmatrix.sync.aligned.m8n8.x4.trans.shared.b16 {%0,%1,%2,%3}, [%4];"
                 : "=r"(r[0]), "=r"(r[1]), "=r"(r[2]), "=r"(r[3]) : "r"(addr));
}
__device__ __forceinline__ void mma_bf16(float* c, const uint32_t* a,
                                         uint32_t b0, uint32_t b1) {
    asm volatile(
        "mma.sync.aligned.m16n8k16.row.col.f32.bf16.bf16.f32 "
        "{%0,%1,%2,%3}, {%4,%5,%6,%7}, {%8,%9}, {%0,%1,%2,%3};"
        : "+f"(c[0]), "+f"(c[1]), "+f"(c[2]), "+f"(c[3])
        : "r"(a[0]), "r"(a[1]), "r"(a[2]), "r"(a[3]), "r"(b0), "r"(b1));
}
__device__ __forceinline__ void cp16(uint32_t dst, const void* src,
                                     uint32_t src_bytes) {
    asm volatile("cp.async.cg.shared.global [%0], [%1], 16, %2;"
                 :: "r"(dst), "l"(src), "r"(src_bytes) : "memory");
}
__device__ __forceinline__ void cp_commit() {
    asm volatile("cp.async.commit_group;" ::: "memory");
}
template <int N>
__device__ __forceinline__ void cp_wait() {
    asm volatile("cp.async.wait_group %0;" :: "n"(N) : "memory");
}

// ---------------------------------------------------------------------------
// Bucketing in smem (proven).
// ---------------------------------------------------------------------------
__device__ void bucket_block_fast(const int* __restrict__ idx32)
{
    __shared__ int w[2 * N_TOK];
    __shared__ int ord[PAD_TOK];
    __shared__ int cnt[NEXP], off[NEXP], cur[NEXP];
    __shared__ int odd_or;
    const int t = threadIdx.x;

    if (t == 0) odd_or = 0;
    if (t < NEXP) { cnt[t] = 0; cur[t] = 0; }

    for (int i = t; i < N_TOK; i += 256) w[i] = idx32[i];
    __syncthreads();

    int lor = 0;
    for (int i = t; i < N_TOK / 2; i += 256) lor |= w[2 * i + 1];
    if (lor) atomicOr(&odd_or, 1);
    __syncthreads();

    const int stride = (odd_or == 0) ? 2 : 1;
    if (stride == 2) {
        for (int i = t; i < N_TOK; i += 256) w[N_TOK + i] = idx32[N_TOK + i];
        __syncthreads();
    }

    for (int i = t; i < N_TOK; i += 256)
        atomicAdd(&cnt[w[i * stride] & (NEXP - 1)], 1);
    for (int i = t; i < PAD_TOK; i += 256) ord[i] = -1;
    __syncthreads();

    if (t == 0) {
        int po = 0, tile = 0;
        for (int e = 0; e < NEXP; e++) {
            off[e] = po;
            int ntl = (cnt[e] + BM - 1) / BM;
            for (int k = 0; k < ntl; k++) g_tile_expert[tile++] = e;
            po += ntl * BM;
        }
        for (; tile < MAX_TILES; tile++) g_tile_expert[tile] = -1;
    }
    __syncthreads();

    for (int i = t; i < N_TOK; i += 256) {
        int e = w[i * stride] & (NEXP - 1);
        ord[off[e] + atomicAdd(&cur[e], 1)] = i;
    }
    __syncthreads();

    for (int i = t; i < PAD_TOK; i += 256) g_order[i] = ord[i];
}

// ---------------------------------------------------------------------------
// Pass 1: block 0 buckets; blocks [1, XCONV] split X into bf16 hi/lo.
// ---------------------------------------------------------------------------
#define XCONV (XELEMS / 8 / 256)   // 512

__global__ void prep_kernel(const float4* __restrict__ X,
                            const int* __restrict__ idx32)
{
    if (blockIdx.x == 0) {
        bucket_block_fast(idx32);
        return;
    }
    const int j = (blockIdx.x - 1) * 256 + threadIdx.x;
    float4 v0 = X[2 * j];
    float4 v1 = X[2 * j + 1];
    float f[8] = {v0.x, v0.y, v0.z, v0.w, v1.x, v1.y, v1.z, v1.w};
    __nv_bfloat16 h[8], l[8];
#pragma unroll
    for (int q = 0; q < 8; q++) {
        h[q] = __float2bfloat16(f[q]);
        l[q] = __float2bfloat16(f[q] - __bfloat162float(h[q]));
    }
    uint4 uh, ul;
    uh.x = ((uint32_t)*(uint16_t*)&h[1] << 16) | *(uint16_t*)&h[0];
    uh.y = ((uint32_t)*(uint16_t*)&h[3] << 16) | *(uint16_t*)&h[2];
    uh.z = ((uint32_t)*(uint16_t*)&h[5] << 16) | *(uint16_t*)&h[4];
    uh.w = ((uint32_t)*(uint16_t*)&h[7] << 16) | *(uint16_t*)&h[6];
    ul.x = ((uint32_t)*(uint16_t*)&l[1] << 16) | *(uint16_t*)&l[0];
    ul.y = ((uint32_t)*(uint16_t*)&l[3] << 16) | *(uint16_t*)&l[2];
    ul.z = ((uint32_t)*(uint16_t*)&l[5] << 16) | *(uint16_t*)&l[4];
    ul.w = ((uint32_t)*(uint16_t*)&l[7] << 16) | *(uint16_t*)&l[6];
    g_Xhi4[j] = uh;
    g_Xlo4[j] = ul;
}

// ---------------------------------------------------------------------------
// Pass 2: HMMA grouped GEMM (CTA 64x32). A via 3-stage cp.async; W fp32
// loaded one chunk ahead, split, STS into double-buffered B tile.
// ---------------------------------------------------------------------------
__device__ __forceinline__ void stage_a(uint32_t sdst, int c,
                                        const __nv_bfloat16* Xhi,
                                        const __nv_bfloat16* Xlo,
                                        const int* toks, int tid)
{
    const int k0 = c * KC;
#pragma unroll
    for (int t = 0; t < 2; t++) {
        int i = tid + t * 128;          // 0..255: 64 rows x 4 vecs
        int row = i >> 2;
        int c8 = (i & 3) * 8;
        int tok = toks[row];
        uint32_t nb = (tok >= 0) ? 16u : 0u;
        size_t src = (size_t)(tok >= 0 ? tok : 0) * DIM + k0 + c8;
        uint32_t d = sdst + (uint32_t)(row * LDSA + c8) * 2;
        cp16(d, Xhi + src, nb);
        cp16(d + (uint32_t)A_LO_E * 2, Xlo + src, nb);
    }
    cp_commit();
}

__device__ __forceinline__ void ldg_b(float4* r, const float* Wf, int c, int tid)
{
    const int k0 = c * KC;
#pragma unroll
    for (int t = 0; t < 2; t++) {
        int i = tid + t * 128;          // 0..255: 32 rows x 8 vecs
        int row = i >> 3;
        int c4 = (i & 7) * 4;
        r[t] = *(const float4*)(Wf + (size_t)(k0 + row) * HOUT + c4);
    }
}

__device__ __forceinline__ void sts_b(uint32_t sbase, int bufsel,
                                      const float4* r, int tid)
{
    const uint32_t base = sbase + (uint32_t)(B0_E + bufsel * B_BUF_E) * 2;
#pragma unroll
    for (int t = 0; t < 2; t++) {
        int i = tid + t * 128;
        int row = i >> 3;
        int c4 = (i & 7) * 4;
        float f[4] = {r[t].x, r[t].y, r[t].z, r[t].w};
        __nv_bfloat16 h[4], l[4];
#pragma unroll
        for (int q = 0; q < 4; q++) {
            h[q] = __float2bfloat16(f[q]);
            l[q] = __float2bfloat16(f[q] - __bfloat162float(h[q]));
        }
        uint32_t uh0 = ((uint32_t)*(uint16_t*)&h[1] << 16) | *(uint16_t*)&h[0];
        uint32_t uh1 = ((uint32_t)*(uint16_t*)&h[3] << 16) | *(uint16_t*)&h[2];
        uint32_t ul0 = ((uint32_t)*(uint16_t*)&l[1] << 16) | *(uint16_t*)&l[0];
        uint32_t ul1 = ((uint32_t)*(uint16_t*)&l[3] << 16) | *(uint16_t*)&l[2];
        uint32_t d = base + (uint32_t)(row * LDSB + c4) * 2;
        asm volatile("st.shared.v2.b32 [%0], {%1, %2};"
                     :: "r"(d), "r"(uh0), "r"(uh1) : "memory");
        asm volatile("st.shared.v2.b32 [%0], {%1, %2};"
                     :: "r"(d + (uint32_t)B_LO_E * 2), "r"(ul0), "r"(ul1)
                     : "memory");
    }
}

__global__ __launch_bounds__(128, 5)
void gemm_hmma_kernel(const float* __restrict__ W,
                      const float* __restrict__ Bv,
                      float* __restrict__ Y)
{
    extern __shared__ __nv_bfloat16 sm[];
    __shared__ int toks[BM];

    const int mt = blockIdx.x;
    const int nt = blockIdx.y;
    const int e  = g_tile_expert[mt];
    if (e < 0) return;

    const int tid = threadIdx.x;
    const int wid = tid >> 5;          // 0..3
    const int lid = tid & 31;
    const int ntb = nt * BN;

    if (tid < BM) toks[tid] = g_order[mt * BM + tid];
    __syncthreads();

    const __nv_bfloat16* Xhi = (const __nv_bfloat16*)g_Xhi4;
    const __nv_bfloat16* Xlo = (const __nv_bfloat16*)g_Xlo4;
    const float* Wf = W + (size_t)e * DIM * HOUT + ntb;

    const int m_base = (wid >> 1) * 32;   // 0 or 32
    const int n_base = (wid & 1) * 16;    // 0 or 16

    const uint32_t sbase = smem_u32(sm);
    const uint32_t aAddr = sbase +
        (uint32_t)((m_base + (lid & 15)) * LDSA + ((lid >> 4) << 3)) * 2;
    const uint32_t bAddr = sbase +
        (uint32_t)(B0_E + (lid & 15) * LDSB + n_base + ((lid >> 4) << 3)) * 2;

    float acc[2][2][4] = {};
    float4 breg[2];

    // prologue
    stage_a(sbase + 0 * A_ST_E * 2, 0, Xhi, Xlo, toks, tid);
    stage_a(sbase + 1 * A_ST_E * 2, 1, Xhi, Xlo, toks, tid);
    ldg_b(breg, Wf, 0, tid);
    sts_b(sbase, 0, breg, tid);
    ldg_b(breg, Wf, 1, tid);

    int abuf = 0;
    for (int c = 0; c < NCHUNK; c++) {
        if (c == NCHUNK - 1) cp_wait<0>(); else cp_wait<1>();
        __syncthreads();
        // All warps are past compute(c-1): safe to fill B buf (c+1)&1 (the
        // buffer compute(c-1) read) and to read A stage c / B buf c&1.

        if (c + 1 < NCHUNK) sts_b(sbase, (c + 1) & 1, breg, tid);

        const uint32_t aoff = (uint32_t)(abuf * A_ST_E) * 2;
        const uint32_t boff = (uint32_t)((c & 1) * B_BUF_E) * 2;

#pragma unroll
        for (int ks = 0; ks < 2; ks++) {
            uint32_t ah[2][4], al[2][4], bh[4], bl[4];
#pragma unroll
            for (int mi = 0; mi < 2; mi++) {
                uint32_t ad = aAddr + aoff + (uint32_t)(mi * 16 * LDSA + ks * 16) * 2;
                ldsm_x4(ah[mi], ad);
                ldsm_x4(al[mi], ad + (uint32_t)A_LO_E * 2);
            }
            {
                uint32_t bd = bAddr + boff + (uint32_t)(ks * 16 * LDSB) * 2;
                ldsm_x4_t(bh, bd);
                ldsm_x4_t(bl, bd + (uint32_t)B_LO_E * 2);
            }
#pragma unroll
            for (int mi = 0; mi < 2; mi++)
#pragma unroll
                for (int ni = 0; ni < 2; ni++) {
                    const int hf = ni * 2;
                    mma_bf16(acc[mi][ni], ah[mi], bh[hf], bh[hf + 1]);
                    mma_bf16(acc[mi][ni], ah[mi], bl[hf], bl[hf + 1]);
                    mma_bf16(acc[mi][ni], al[mi], bh[hf], bh[hf + 1]);
                }
        }

        if (c + 2 < NCHUNK) {
            ldg_b(breg, Wf, c + 2, tid);
            int nbuf = abuf + 2; if (nbuf >= NSTAGE) nbuf -= NSTAGE;
            stage_a(sbase + (uint32_t)(nbuf * A_ST_E) * 2, c + 2, Xhi, Xlo, toks, tid);
        }
        if (++abuf == NSTAGE) abuf = 0;
    }

    // epilogue: bias + gathered store
#pragma unroll
    for (int mi = 0; mi < 2; mi++) {
        const int r0 = m_base + mi * 16 + (lid >> 2);
        const int tok0 = toks[r0];
        const int tok1 = toks[r0 + 8];
#pragma unroll
        for (int ni = 0; ni < 2; ni++) {
            const int col = ntb + n_base + ni * 8 + (lid & 3) * 2;
            const float2 b2 = *(const float2*)(Bv + (size_t)e * HOUT + col);
            if (tok0 >= 0) {
                float2 o = {acc[mi][ni][0] + b2.x, acc[mi][ni][1] + b2.y};
                *(float2*)(Y + (size_t)tok0 * HOUT + col) = o;
            }
            if (tok1 >= 0) {
                float2 o = {acc[mi][ni][2] + b2.x, acc[mi][ni][3] + b2.y};
                *(float2*)(Y + (size_t)tok1 * HOUT + col) = o;
            }
        }
    }
}

extern "C" void kernel_launch(void* const* d_in, const int* in_sizes, int n_in,
                              void* d_out, int out_size)
{
    const float* X   = (const float*)d_in[0];   // inputs (2048, 512) f32
    const int*   idx = (const int*)d_in[1];     // idx (2048) i32/i64 autodetect
    const float* W   = (const float*)d_in[2];   // weights (16, 512, 512) f32
    const float* Bv  = (const float*)d_in[3];   // biases (16, 512) f32
    float*       Y   = (float*)d_out;           // out (2048, 512) f32

    cudaFuncSetAttribute(gemm_hmma_kernel,
                         cudaFuncAttributeMaxDynamicSharedMemorySize, SMEM_BYTES);

    prep_kernel<<<XCONV + 1, 256>>>((const float4*)X, idx);

    dim3 grid(MAX_TILES, HOUT / BN);
    gemm_hmma_kernel<<<grid, 128, SMEM_BYTES>>>(W, Bv, Y);
}

// round 13
// speedup vs baseline: 1.0665x; 1.0665x over previous
#include <cuda_runtime.h>
#include <cuda_bf16.h>
#include <stdint.h>

// Problem constants
#define N_TOK   2048
#define DIM     512
#define HOUT    512
#define NEXP    16

// GEMM tiling: CTA 64x64, 4 warps of 32x32
#define BM      64
#define BN      64
#define KC      32
#define NCHUNK  (DIM / KC)   // 16
#define NSTAGE  3            // A-tile cp.async stages
#define MAX_TILES 48         // 2048/64 + 16 worst case
#define PAD_TOK (MAX_TILES * BM)   // 3072

// smem layout (bf16 elems)
#define LDSA    40                          // KC+8 pad
#define LDSB    72                          // BN+8 pad (proven conflict-free)
#define A_ST_E  (2 * BM * LDSA)             // hi+lo per A stage = 5120
#define A_LO_E  (BM * LDSA)                 // 2560 (offset of lo within stage)
#define B0_E    (NSTAGE * A_ST_E)           // 15360
#define B_BUF_E (2 * KC * LDSB)             // hi+lo per B buf = 4608
#define B_LO_E  (KC * LDSB)                 // 2304
#define SMEM_BYTES ((B0_E + 2 * B_BUF_E) * 2)   // 49152

// X split scratch (W is converted on the fly)
#define XELEMS (N_TOK * DIM)
__device__ uint4 g_Xhi4[XELEMS / 8];
__device__ uint4 g_Xlo4[XELEMS / 8];

__device__ int g_order[PAD_TOK];
__device__ int g_tile_expert[MAX_TILES];

// ---------------------------------------------------------------------------
// PTX helpers (sm_80-era only; tcgen05 is gated off by the sm_103 ptxas target)
// ---------------------------------------------------------------------------
__device__ __forceinline__ uint32_t smem_u32(const void* p) {
    uint32_t a;
    asm("{ .reg .u64 t; cvta.to.shared.u64 t, %1; cvt.u32.u64 %0, t; }"
        : "=r"(a) : "l"(p));
    return a;
}
__device__ __forceinline__ void ldsm_x4(uint32_t* r, uint32_t addr) {
    asm volatile("ldmatrix.sync.aligned.m8n8.x4.shared.b16 {%0,%1,%2,%3}, [%4];"
                 : "=r"(r[0]), "=r"(r[1]), "=r"(r[2]), "=r"(r[3]) : "r"(addr));
}
__device__ __forceinline__ void ldsm_x4_t(uint32_t* r, uint32_t addr) {
    asm volatile("ldmatrix.sync.aligned.m8n8.x4.trans.shared.b16 {%0,%1,%2,%3}, [%4];"
                 : "=r"(r[0]), "=r"(r[1]), "=r"(r[2]), "=r"(r[3]) : "r"(addr));
}
__device__ __forceinline__ void mma_bf16(float* c, const uint32_t* a,
                                         uint32_t b0, uint32_t b1) {
    asm volatile(
        "mma.sync.aligned.m16n8k16.row.col.f32.bf16.bf16.f32 "
        "{%0,%1,%2,%3}, {%4,%5,%6,%7}, {%8,%9}, {%0,%1,%2,%3};"
        : "+f"(c[0]), "+f"(c[1]), "+f"(c[2]), "+f"(c[3])
        : "r"(a[0]), "r"(a[1]), "r"(a[2]), "r"(a[3]), "r"(b0), "r"(b1));
}
__device__ __forceinline__ void cp16(uint32_t dst, const void* src,
                                     uint32_t src_bytes) {
    asm volatile("cp.async.cg.shared.global [%0], [%1], 16, %2;"
                 :: "r"(dst), "l"(src), "r"(src_bytes) : "memory");
}
__device__ __forceinline__ void cp_commit() {
    asm volatile("cp.async.commit_group;" ::: "memory");
}
template <int N>
__device__ __forceinline__ void cp_wait() {
    asm volatile("cp.async.wait_group %0;" :: "n"(N) : "memory");
}

// ---------------------------------------------------------------------------
// Bucketing in smem (proven).
// ---------------------------------------------------------------------------
__device__ void bucket_block_fast(const int* __restrict__ idx32)
{
    __shared__ int w[2 * N_TOK];
    __shared__ int ord[PAD_TOK];
    __shared__ int cnt[NEXP], off[NEXP], cur[NEXP];
    __shared__ int odd_or;
    const int t = threadIdx.x;

    if (t == 0) odd_or = 0;
    if (t < NEXP) { cnt[t] = 0; cur[t] = 0; }

    for (int i = t; i < N_TOK; i += 256) w[i] = idx32[i];
    __syncthreads();

    int lor = 0;
    for (int i = t; i < N_TOK / 2; i += 256) lor |= w[2 * i + 1];
    if (lor) atomicOr(&odd_or, 1);
    __syncthreads();

    const int stride = (odd_or == 0) ? 2 : 1;
    if (stride == 2) {
        for (int i = t; i < N_TOK; i += 256) w[N_TOK + i] = idx32[N_TOK + i];
        __syncthreads();
    }

    for (int i = t; i < N_TOK; i += 256)
        atomicAdd(&cnt[w[i * stride] & (NEXP - 1)], 1);
    for (int i = t; i < PAD_TOK; i += 256) ord[i] = -1;
    __syncthreads();

    if (t == 0) {
        int po = 0, tile = 0;
        for (int e = 0; e < NEXP; e++) {
            off[e] = po;
            int ntl = (cnt[e] + BM - 1) / BM;
            for (int k = 0; k < ntl; k++) g_tile_expert[tile++] = e;
            po += ntl * BM;
        }
        for (; tile < MAX_TILES; tile++) g_tile_expert[tile] = -1;
    }
    __syncthreads();

    for (int i = t; i < N_TOK; i += 256) {
        int e = w[i * stride] & (NEXP - 1);
        ord[off[e] + atomicAdd(&cur[e], 1)] = i;
    }
    __syncthreads();

    for (int i = t; i < PAD_TOK; i += 256) g_order[i] = ord[i];
}

// ---------------------------------------------------------------------------
// Pass 1: block 0 buckets; blocks [1, XCONV] split X into bf16 hi/lo.
// ---------------------------------------------------------------------------
#define XCONV (XELEMS / 8 / 256)   // 512

__global__ void prep_kernel(const float4* __restrict__ X,
                            const int* __restrict__ idx32)
{
    if (blockIdx.x == 0) {
        bucket_block_fast(idx32);
        return;
    }
    const int j = (blockIdx.x - 1) * 256 + threadIdx.x;
    float4 v0 = X[2 * j];
    float4 v1 = X[2 * j + 1];
    float f[8] = {v0.x, v0.y, v0.z, v0.w, v1.x, v1.y, v1.z, v1.w};
    __nv_bfloat16 h[8], l[8];
#pragma unroll
    for (int q = 0; q < 8; q++) {
        h[q] = __float2bfloat16(f[q]);
        l[q] = __float2bfloat16(f[q] - __bfloat162float(h[q]));
    }
    uint4 uh, ul;
    uh.x = ((uint32_t)*(uint16_t*)&h[1] << 16) | *(uint16_t*)&h[0];
    uh.y = ((uint32_t)*(uint16_t*)&h[3] << 16) | *(uint16_t*)&h[2];
    uh.z = ((uint32_t)*(uint16_t*)&h[5] << 16) | *(uint16_t*)&h[4];
    uh.w = ((uint32_t)*(uint16_t*)&h[7] << 16) | *(uint16_t*)&h[6];
    ul.x = ((uint32_t)*(uint16_t*)&l[1] << 16) | *(uint16_t*)&l[0];
    ul.y = ((uint32_t)*(uint16_t*)&l[3] << 16) | *(uint16_t*)&l[2];
    ul.z = ((uint32_t)*(uint16_t*)&l[5] << 16) | *(uint16_t*)&l[4];
    ul.w = ((uint32_t)*(uint16_t*)&l[7] << 16) | *(uint16_t*)&l[6];
    g_Xhi4[j] = uh;
    g_Xlo4[j] = ul;
}

// ---------------------------------------------------------------------------
// Pass 2: HMMA grouped GEMM (CTA 64x64). A via 3-stage cp.async; W fp32
// loaded one chunk ahead, split, STS into double-buffered B tile.
// MMA issue order is TERM-MAJOR (all hi*hi, then hi*lo, then lo*hi) so that
// consecutive HMMAs never share an accumulator (acc-RAW chain was the wall).
// ---------------------------------------------------------------------------
__device__ __forceinline__ void stage_a(uint32_t sdst, int c,
                                        const __nv_bfloat16* Xhi,
                                        const __nv_bfloat16* Xlo,
                                        const int* toks, int tid)
{
    const int k0 = c * KC;
#pragma unroll
    for (int t = 0; t < 2; t++) {
        int i = tid + t * 128;          // 0..255: 64 rows x 4 vecs
        int row = i >> 2;
        int c8 = (i & 3) * 8;
        int tok = toks[row];
        uint32_t nb = (tok >= 0) ? 16u : 0u;
        size_t src = (size_t)(tok >= 0 ? tok : 0) * DIM + k0 + c8;
        uint32_t d = sdst + (uint32_t)(row * LDSA + c8) * 2;
        cp16(d, Xhi + src, nb);
        cp16(d + (uint32_t)A_LO_E * 2, Xlo + src, nb);
    }
    cp_commit();
}

__device__ __forceinline__ void ldg_b(float4* r, const float* Wf, int c, int tid)
{
    const int k0 = c * KC;
#pragma unroll
    for (int t = 0; t < 4; t++) {
        int i = tid + t * 128;          // 0..511: 32 rows x 16 vecs
        int row = i >> 4;
        int c4 = (i & 15) * 4;
        r[t] = *(const float4*)(Wf + (size_t)(k0 + row) * HOUT + c4);
    }
}

__device__ __forceinline__ void sts_b(uint32_t sbase, int bufsel,
                                      const float4* r, int tid)
{
    const uint32_t base = sbase + (uint32_t)(B0_E + bufsel * B_BUF_E) * 2;
#pragma unroll
    for (int t = 0; t < 4; t++) {
        int i = tid + t * 128;
        int row = i >> 4;
        int c4 = (i & 15) * 4;
        float f[4] = {r[t].x, r[t].y, r[t].z, r[t].w};
        __nv_bfloat16 h[4], l[4];
#pragma unroll
        for (int q = 0; q < 4; q++) {
            h[q] = __float2bfloat16(f[q]);
            l[q] = __float2bfloat16(f[q] - __bfloat162float(h[q]));
        }
        uint32_t uh0 = ((uint32_t)*(uint16_t*)&h[1] << 16) | *(uint16_t*)&h[0];
        uint32_t uh1 = ((uint32_t)*(uint16_t*)&h[3] << 16) | *(uint16_t*)&h[2];
        uint32_t ul0 = ((uint32_t)*(uint16_t*)&l[1] << 16) | *(uint16_t*)&l[0];
        uint32_t ul1 = ((uint32_t)*(uint16_t*)&l[3] << 16) | *(uint16_t*)&l[2];
        uint32_t d = base + (uint32_t)(row * LDSB + c4) * 2;
        asm volatile("st.shared.v2.b32 [%0], {%1, %2};"
                     :: "r"(d), "r"(uh0), "r"(uh1) : "memory");
        asm volatile("st.shared.v2.b32 [%0], {%1, %2};"
                     :: "r"(d + (uint32_t)B_LO_E * 2), "r"(ul0), "r"(ul1)
                     : "memory");
    }
}

__global__ __launch_bounds__(128, 4)
void gemm_hmma_kernel(const float* __restrict__ W,
                      const float* __restrict__ Bv,
                      float* __restrict__ Y)
{
    extern __shared__ __nv_bfloat16 sm[];
    __shared__ int toks[BM];

    const int mt = blockIdx.x;
    const int nt = blockIdx.y;
    const int e  = g_tile_expert[mt];
    if (e < 0) return;

    const int tid = threadIdx.x;
    const int wid = tid >> 5;          // 0..3
    const int lid = tid & 31;
    const int ntb = nt * BN;

    if (tid < BM) toks[tid] = g_order[mt * BM + tid];
    __syncthreads();

    const __nv_bfloat16* Xhi = (const __nv_bfloat16*)g_Xhi4;
    const __nv_bfloat16* Xlo = (const __nv_bfloat16*)g_Xlo4;
    const float* Wf = W + (size_t)e * DIM * HOUT + ntb;

    const int m_base = (wid >> 1) * 32;
    const int n_base = (wid & 1) * 32;

    const uint32_t sbase = smem_u32(sm);
    const uint32_t aAddr = sbase +
        (uint32_t)((m_base + (lid & 15)) * LDSA + ((lid >> 4) << 3)) * 2;
    const uint32_t bAddr = sbase +
        (uint32_t)(B0_E + (lid & 15) * LDSB + n_base + ((lid >> 4) << 3)) * 2;

    float acc[2][4][4] = {};
    float4 breg[4];

    // prologue
    stage_a(sbase + 0 * A_ST_E * 2, 0, Xhi, Xlo, toks, tid);
    stage_a(sbase + 1 * A_ST_E * 2, 1, Xhi, Xlo, toks, tid);
    ldg_b(breg, Wf, 0, tid);
    sts_b(sbase, 0, breg, tid);
    ldg_b(breg, Wf, 1, tid);

    int abuf = 0;
    for (int c = 0; c < NCHUNK; c++) {
        if (c == NCHUNK - 1) cp_wait<0>(); else cp_wait<1>();
        __syncthreads();
        // All warps are past compute(c-1): safe to fill B buf (c+1)&1 (the
        // buffer compute(c-1) read) and to read A stage c / B buf c&1.

        if (c + 1 < NCHUNK) sts_b(sbase, (c + 1) & 1, breg, tid);

        const uint32_t aoff = (uint32_t)(abuf * A_ST_E) * 2;
        const uint32_t boff = (uint32_t)((c & 1) * B_BUF_E) * 2;

#pragma unroll
        for (int ks = 0; ks < 2; ks++) {
            uint32_t ah[2][4], al[2][4], bh[2][4], bl[2][4];
#pragma unroll
            for (int mi = 0; mi < 2; mi++) {
                uint32_t ad = aAddr + aoff + (uint32_t)(mi * 16 * LDSA + ks * 16) * 2;
                ldsm_x4(ah[mi], ad);
                ldsm_x4(al[mi], ad + (uint32_t)A_LO_E * 2);
            }
#pragma unroll
            for (int np = 0; np < 2; np++) {
                uint32_t bd = bAddr + boff + (uint32_t)(ks * 16 * LDSB + np * 16) * 2;
                ldsm_x4_t(bh[np], bd);
                ldsm_x4_t(bl[np], bd + (uint32_t)B_LO_E * 2);
            }
            // term-major: 8 independent accumulators between same-acc reuses
#pragma unroll
            for (int mi = 0; mi < 2; mi++)
#pragma unroll
                for (int ni = 0; ni < 4; ni++) {
                    const int np = ni >> 1, hf = (ni & 1) * 2;
                    mma_bf16(acc[mi][ni], ah[mi], bh[np][hf], bh[np][hf + 1]);
                }
#pragma unroll
            for (int mi = 0; mi < 2; mi++)
#pragma unroll
                for (int ni = 0; ni < 4; ni++) {
                    const int np = ni >> 1, hf = (ni & 1) * 2;
                    mma_bf16(acc[mi][ni], ah[mi], bl[np][hf], bl[np][hf + 1]);
                }
#pragma unroll
            for (int mi = 0; mi < 2; mi++)
#pragma unroll
                for (int ni = 0; ni < 4; ni++) {
                    const int np = ni >> 1, hf = (ni & 1) * 2;
                    mma_bf16(acc[mi][ni], al[mi], bh[np][hf], bh[np][hf + 1]);
                }
        }

        if (c + 2 < NCHUNK) {
            ldg_b(breg, Wf, c + 2, tid);
            int nbuf = abuf + 2; if (nbuf >= NSTAGE) nbuf -= NSTAGE;
            stage_a(sbase + (uint32_t)(nbuf * A_ST_E) * 2, c + 2, Xhi, Xlo, toks, tid);
        }
        if (++abuf == NSTAGE) abuf = 0;
    }

    // epilogue: bias + gathered store
#pragma unroll
    for (int mi = 0; mi < 2; mi++) {
        const int r0 = m_base + mi * 16 + (lid >> 2);
        const int tok0 = toks[r0];
        const int tok1 = toks[r0 + 8];
#pragma unroll
        for (int ni = 0; ni < 4; ni++) {
            const int col = ntb + n_base + ni * 8 + (lid & 3) * 2;
            const float2 b2 = *(const float2*)(Bv + (size_t)e * HOUT + col);
            if (tok0 >= 0) {
                float2 o = {acc[mi][ni][0] + b2.x, acc[mi][ni][1] + b2.y};
                *(float2*)(Y + (size_t)tok0 * HOUT + col) = o;
            }
            if (tok1 >= 0) {
                float2 o = {acc[mi][ni][2] + b2.x, acc[mi][ni][3] + b2.y};
                *(float2*)(Y + (size_t)tok1 * HOUT + col) = o;
            }
        }
    }
}

extern "C" void kernel_launch(void* const* d_in, const int* in_sizes, int n_in,
                              void* d_out, int out_size)
{
    const float* X   = (const float*)d_in[0];   // inputs (2048, 512) f32
    const int*   idx = (const int*)d_in[1];     // idx (2048) i32/i64 autodetect
    const float* W   = (const float*)d_in[2];   // weights (16, 512, 512) f32
    const float* Bv  = (const float*)d_in[3];   // biases (16, 512) f32
    float*       Y   = (float*)d_out;           // out (2048, 512) f32

    cudaFuncSetAttribute(gemm_hmma_kernel,
                         cudaFuncAttributeMaxDynamicSharedMemorySize, SMEM_BYTES);

    prep_kernel<<<XCONV + 1, 256>>>((const float4*)X, idx);

    dim3 grid(MAX_TILES, HOUT / BN);
    gemm_hmma_kernel<<<grid, 128, SMEM_BYTES>>>(W, Bv, Y);
}